// round 6
// baseline (speedup 1.0000x reference)
#include <cuda_runtime.h>
#include <math_constants.h>

#define SEQ    2048
#define BATCH  2
#define NHEADS 8
#define DMODEL 512
#define HDIM   64

// Scratch (allocation-free): 4 x 8MB
__device__ float g_Q[BATCH * SEQ * DMODEL];
__device__ float g_K[BATCH * SEQ * DMODEL];
__device__ float g_V[BATCH * SEQ * DMODEL];
__device__ float g_CTX[BATCH * SEQ * DMODEL];

// ---------------------------------------------------------------------------
// Y[M,N] = (X[M,K] @ W[K,N] + bias[N]) * scale
// 128x128 tile, BK=16, 256 threads, 8x8 micro-tile per thread.
// ---------------------------------------------------------------------------
__global__ __launch_bounds__(256) void gemm_bias_kernel(
    const float* __restrict__ X, const float* __restrict__ W,
    const float* __restrict__ bias, float* __restrict__ Y,
    int M, int N, int K, float scale)
{
    __shared__ float As[16][128];   // A transposed: [k][m]
    __shared__ float Bs[16][128];   // B natural:    [k][n]

    const int bm  = blockIdx.y * 128;
    const int bn  = blockIdx.x * 128;
    const int tid = threadIdx.x;
    const int row = (tid >> 4) * 8;   // 0..120
    const int col = (tid & 15) * 8;   // 0..120

    float acc[8][8];
#pragma unroll
    for (int i = 0; i < 8; i++)
#pragma unroll
        for (int j = 0; j < 8; j++) acc[i][j] = 0.f;

    for (int k0 = 0; k0 < K; k0 += 16) {
        // Load A tile (128 rows x 16 k) as float4 along k, scatter-transpose.
#pragma unroll
        for (int it = 0; it < 2; it++) {
            int idx = tid + it * 256;          // 0..511 float4 chunks
            int r   = idx >> 2;                // 0..127
            int c4  = (idx & 3) << 2;          // 0,4,8,12
            float4 v = *(const float4*)&X[(size_t)(bm + r) * K + k0 + c4];
            As[c4 + 0][r] = v.x; As[c4 + 1][r] = v.y;
            As[c4 + 2][r] = v.z; As[c4 + 3][r] = v.w;
        }
        // Load B tile (16 k x 128 n), natural layout.
#pragma unroll
        for (int it = 0; it < 2; it++) {
            int idx = tid + it * 256;
            int r   = idx >> 5;                // 0..15
            int c4  = (idx & 31) << 2;         // 0..124
            *(float4*)&Bs[r][c4] = *(const float4*)&W[(size_t)(k0 + r) * N + bn + c4];
        }
        __syncthreads();

#pragma unroll
        for (int k = 0; k < 16; k++) {
            float a[8], b[8];
            *(float4*)&a[0] = *(float4*)&As[k][row];
            *(float4*)&a[4] = *(float4*)&As[k][row + 4];
            *(float4*)&b[0] = *(float4*)&Bs[k][col];
            *(float4*)&b[4] = *(float4*)&Bs[k][col + 4];
#pragma unroll
            for (int i = 0; i < 8; i++)
#pragma unroll
                for (int j = 0; j < 8; j++) acc[i][j] += a[i] * b[j];
        }
        __syncthreads();
    }

#pragma unroll
    for (int i = 0; i < 8; i++) {
        float4 o0, o1;
        o0.x = (acc[i][0] + bias[bn + col + 0]) * scale;
        o0.y = (acc[i][1] + bias[bn + col + 1]) * scale;
        o0.z = (acc[i][2] + bias[bn + col + 2]) * scale;
        o0.w = (acc[i][3] + bias[bn + col + 3]) * scale;
        o1.x = (acc[i][4] + bias[bn + col + 4]) * scale;
        o1.y = (acc[i][5] + bias[bn + col + 5]) * scale;
        o1.z = (acc[i][6] + bias[bn + col + 6]) * scale;
        o1.w = (acc[i][7] + bias[bn + col + 7]) * scale;
        *(float4*)&Y[(size_t)(bm + row + i) * N + bn + col + 0] = o0;
        *(float4*)&Y[(size_t)(bm + row + i) * N + bn + col + 4] = o1;
    }
}

// ---------------------------------------------------------------------------
// Fused flash attention: per CTA = (64 q-rows, one head, one batch).
// Online softmax with additive bias and boolean mask (mask stored as int32).
// Writes ctx in [b, s, h*64+d] layout (ready for output projection).
// ---------------------------------------------------------------------------
__global__ __launch_bounds__(256) void flash_attn_kernel(
    const int* __restrict__ mask,
    const float* __restrict__ bias)
{
    __shared__ float Qt[64][64];    // [d][q-row]
    __shared__ float KtP[64][64];   // phase 1: Kt [d][k-row]; phase 2: P [q-row][k-col]
    __shared__ float Vs[64][64];    // [k-row][d]

    const int q0  = blockIdx.x * 64;
    const int h   = blockIdx.y;
    const int b   = blockIdx.z;
    const int tid = threadIdx.x;
    const int tr  = tid >> 4;       // 0..15
    const int tc  = tid & 15;       // 0..15
    const int r0  = tr * 4;
    const int c0  = tc * 4;

    const float* Qg = g_Q + (size_t)b * SEQ * DMODEL + (size_t)h * HDIM;
    const float* Kg = g_K + (size_t)b * SEQ * DMODEL + (size_t)h * HDIM;
    const float* Vg = g_V + (size_t)b * SEQ * DMODEL + (size_t)h * HDIM;
    const float* biasH = bias + (size_t)h * SEQ * SEQ;

    // Load Q tile transposed.
    for (int idx = tid; idx < 1024; idx += 256) {
        int r  = idx >> 4;          // 0..63
        int c4 = (idx & 15) << 2;   // 0..60
        float4 v = *(const float4*)&Qg[(size_t)(q0 + r) * DMODEL + c4];
        Qt[c4 + 0][r] = v.x; Qt[c4 + 1][r] = v.y;
        Qt[c4 + 2][r] = v.z; Qt[c4 + 3][r] = v.w;
    }

    float m_i[4], l_i[4], O[4][4];
#pragma unroll
    for (int i = 0; i < 4; i++) {
        m_i[i] = -CUDART_INF_F;
        l_i[i] = 0.f;
#pragma unroll
        for (int j = 0; j < 4; j++) O[i][j] = 0.f;
    }

    for (int k0 = 0; k0 < SEQ; k0 += 64) {
        // Load K tile (transposed) and V tile (natural).
        for (int idx = tid; idx < 1024; idx += 256) {
            int r  = idx >> 4;
            int c4 = (idx & 15) << 2;
            float4 kv = *(const float4*)&Kg[(size_t)(k0 + r) * DMODEL + c4];
            KtP[c4 + 0][r] = kv.x; KtP[c4 + 1][r] = kv.y;
            KtP[c4 + 2][r] = kv.z; KtP[c4 + 3][r] = kv.w;
            *(float4*)&Vs[r][c4] = *(const float4*)&Vg[(size_t)(k0 + r) * DMODEL + c4];
        }
        __syncthreads();

        // Scores: s[4][4] = Q_tile(r0..r0+3) . K_tile(c0..c0+3)
        float s[4][4];
#pragma unroll
        for (int i = 0; i < 4; i++)
#pragma unroll
            for (int j = 0; j < 4; j++) s[i][j] = 0.f;

#pragma unroll 8
        for (int d = 0; d < 64; d++) {
            float4 a  = *(float4*)&Qt[d][r0];
            float4 bb = *(float4*)&KtP[d][c0];
            s[0][0] += a.x * bb.x; s[0][1] += a.x * bb.y; s[0][2] += a.x * bb.z; s[0][3] += a.x * bb.w;
            s[1][0] += a.y * bb.x; s[1][1] += a.y * bb.y; s[1][2] += a.y * bb.z; s[1][3] += a.y * bb.w;
            s[2][0] += a.z * bb.x; s[2][1] += a.z * bb.y; s[2][2] += a.z * bb.z; s[2][3] += a.z * bb.w;
            s[3][0] += a.w * bb.x; s[3][1] += a.w * bb.y; s[3][2] += a.w * bb.z; s[3][3] += a.w * bb.w;
        }

        // Bias + mask (mask is int32 0/1).
#pragma unroll
        for (int ii = 0; ii < 4; ii++) {
            size_t off = (size_t)(q0 + r0 + ii) * SEQ + k0 + c0;
            float4 bv = *(const float4*)&biasH[off];
            int4   mv = *(const int4*)&mask[off];
            s[ii][0] = mv.x ? (s[ii][0] + bv.x) : -CUDART_INF_F;
            s[ii][1] = mv.y ? (s[ii][1] + bv.y) : -CUDART_INF_F;
            s[ii][2] = mv.z ? (s[ii][2] + bv.z) : -CUDART_INF_F;
            s[ii][3] = mv.w ? (s[ii][3] + bv.w) : -CUDART_INF_F;
        }

        // Online softmax update (row-groups are 16 consecutive lanes).
        float p[4][4];
#pragma unroll
        for (int ii = 0; ii < 4; ii++) {
            float rm = fmaxf(fmaxf(s[ii][0], s[ii][1]), fmaxf(s[ii][2], s[ii][3]));
#pragma unroll
            for (int off = 1; off < 16; off <<= 1)
                rm = fmaxf(rm, __shfl_xor_sync(0xffffffffu, rm, off));
            float mnew = fmaxf(m_i[ii], rm);
            float alpha, rs;
            if (mnew == -CUDART_INF_F) {   // whole row masked so far
                alpha = 1.f;
                p[ii][0] = p[ii][1] = p[ii][2] = p[ii][3] = 0.f;
                rs = 0.f;
            } else {
                alpha = __expf(m_i[ii] - mnew);   // exp(-inf)=0 handled
                p[ii][0] = __expf(s[ii][0] - mnew);
                p[ii][1] = __expf(s[ii][1] - mnew);
                p[ii][2] = __expf(s[ii][2] - mnew);
                p[ii][3] = __expf(s[ii][3] - mnew);
                rs = p[ii][0] + p[ii][1] + p[ii][2] + p[ii][3];
#pragma unroll
                for (int off = 1; off < 16; off <<= 1)
                    rs += __shfl_xor_sync(0xffffffffu, rs, off);
            }
            m_i[ii] = mnew;
            l_i[ii] = l_i[ii] * alpha + rs;
            O[ii][0] *= alpha; O[ii][1] *= alpha; O[ii][2] *= alpha; O[ii][3] *= alpha;
        }

        __syncthreads();   // everyone done reading Kt
        // Write P into the Kt buffer: P[q-row][k-col]
#pragma unroll
        for (int ii = 0; ii < 4; ii++)
#pragma unroll
            for (int jj = 0; jj < 4; jj++)
                KtP[r0 + ii][c0 + jj] = p[ii][jj];
        __syncthreads();

        // O += P @ V  (rows r0.., d-cols c0..)
#pragma unroll 8
        for (int j = 0; j < 64; j++) {
            float a0 = KtP[r0 + 0][j];
            float a1 = KtP[r0 + 1][j];
            float a2 = KtP[r0 + 2][j];
            float a3 = KtP[r0 + 3][j];
            float4 vv = *(float4*)&Vs[j][c0];
            O[0][0] += a0 * vv.x; O[0][1] += a0 * vv.y; O[0][2] += a0 * vv.z; O[0][3] += a0 * vv.w;
            O[1][0] += a1 * vv.x; O[1][1] += a1 * vv.y; O[1][2] += a1 * vv.z; O[1][3] += a1 * vv.w;
            O[2][0] += a2 * vv.x; O[2][1] += a2 * vv.y; O[2][2] += a2 * vv.z; O[2][3] += a2 * vv.w;
            O[3][0] += a3 * vv.x; O[3][1] += a3 * vv.y; O[3][2] += a3 * vv.z; O[3][3] += a3 * vv.w;
        }
        __syncthreads();   // before next tile's loads overwrite KtP/Vs
    }

    // Normalize and write ctx in [b, s, h*64 + d] layout.
#pragma unroll
    for (int ii = 0; ii < 4; ii++) {
        float inv = (l_i[ii] > 0.f) ? (1.f / l_i[ii]) : 0.f;
        float4 o;
        o.x = O[ii][0] * inv; o.y = O[ii][1] * inv;
        o.z = O[ii][2] * inv; o.w = O[ii][3] * inv;
        size_t out_off = (size_t)(b * SEQ + q0 + r0 + ii) * DMODEL + h * HDIM + c0;
        *(float4*)&g_CTX[out_off] = o;
    }
}

// ---------------------------------------------------------------------------
// Launch
// ---------------------------------------------------------------------------
extern "C" void kernel_launch(void* const* d_in, const int* in_sizes, int n_in,
                              void* d_out, int out_size)
{
    const float* k    = (const float*)d_in[0];
    const float* v    = (const float*)d_in[1];
    const float* q    = (const float*)d_in[2];
    const int*   mask = (const int*)d_in[3];
    const float* bias = (const float*)d_in[4];
    const float* Wq   = (const float*)d_in[5];
    const float* bq   = (const float*)d_in[6];
    const float* Wk   = (const float*)d_in[7];
    const float* bk   = (const float*)d_in[8];
    const float* Wv   = (const float*)d_in[9];
    const float* bv   = (const float*)d_in[10];
    const float* Wo   = (const float*)d_in[11];
    const float* bo   = (const float*)d_in[12];
    float* out = (float*)d_out;

    float *pQ, *pK, *pV, *pC;
    cudaGetSymbolAddress((void**)&pQ, g_Q);
    cudaGetSymbolAddress((void**)&pK, g_K);
    cudaGetSymbolAddress((void**)&pV, g_V);
    cudaGetSymbolAddress((void**)&pC, g_CTX);

    const int M = BATCH * SEQ;         // 4096
    dim3 gemm_grid(DMODEL / 128, M / 128);   // (4, 32)
    const float qscale = 0.125f;       // 1/sqrt(64)

    gemm_bias_kernel<<<gemm_grid, 256>>>(q, Wq, bq, pQ, M, DMODEL, DMODEL, qscale);
    gemm_bias_kernel<<<gemm_grid, 256>>>(k, Wk, bk, pK, M, DMODEL, DMODEL, 1.0f);
    gemm_bias_kernel<<<gemm_grid, 256>>>(v, Wv, bv, pV, M, DMODEL, DMODEL, 1.0f);

    dim3 attn_grid(SEQ / 64, NHEADS, BATCH);  // (32, 8, 2)
    flash_attn_kernel<<<attn_grid, 256>>>(mask, bias);

    gemm_bias_kernel<<<gemm_grid, 256>>>(pC, Wo, bo, out, M, DMODEL, DMODEL, 1.0f);
}

// round 8
// speedup vs baseline: 1.7236x; 1.7236x over previous
#include <cuda_runtime.h>
#include <math_constants.h>
#include <cstdint>

#define SEQ    2048
#define BATCH  2
#define NHEADS 8
#define DMODEL 512
#define HDIM   64

// Scratch (allocation-free): 4 x 8MB
__device__ float g_Q[BATCH * SEQ * DMODEL];
__device__ float g_K[BATCH * SEQ * DMODEL];
__device__ float g_V[BATCH * SEQ * DMODEL];
__device__ float g_CTX[BATCH * SEQ * DMODEL];

// ---------------------------------------------------------------------------
// tf32 helpers
// ---------------------------------------------------------------------------
__device__ __forceinline__ float tf32hi(float x) {
    uint32_t u;
    asm("cvt.rna.tf32.f32 %0, %1;" : "=r"(u) : "f"(x));
    return __uint_as_float(u);
}

// D += A * B  (m16n8k8, row.col, tf32 in / f32 accum)
__device__ __forceinline__ void mma8(float* c, const uint32_t* a, const uint32_t* b) {
    asm volatile(
        "mma.sync.aligned.m16n8k8.row.col.f32.tf32.tf32.f32 "
        "{%0,%1,%2,%3}, {%4,%5,%6,%7}, {%8,%9}, {%0,%1,%2,%3};"
        : "+f"(c[0]), "+f"(c[1]), "+f"(c[2]), "+f"(c[3])
        : "r"(a[0]), "r"(a[1]), "r"(a[2]), "r"(a[3]), "r"(b[0]), "r"(b[1]));
}

// ---------------------------------------------------------------------------
// 3xTF32 GEMM: Y[M,N] = (X[M,K] @ W[K,N] + bias[N]) * scale
// 128x128 tile, BK=32, 256 threads = 8 warps (4m x 2n), warp tile 32x64.
// ---------------------------------------------------------------------------
#define SA 36    // A smem row stride (floats)
#define SB 136   // B smem row stride (floats)

__global__ __launch_bounds__(256) void gemm_tf32_kernel(
    const float* __restrict__ X, const float* __restrict__ W,
    const float* __restrict__ bias, float* __restrict__ Y,
    int M, int N, int K, float scale)
{
    extern __shared__ float sm[];
    float* Ah = sm;                       // [128][SA]
    float* Al = sm + 128 * SA;
    float* Bh = sm + 2 * 128 * SA;        // [32][SB]
    float* Bl = sm + 2 * 128 * SA + 32 * SB;

    const int bm   = blockIdx.y * 128;
    const int bn   = blockIdx.x * 128;
    const int tid  = threadIdx.x;
    const int warp = tid >> 5;
    const int lane = tid & 31;
    const int g    = lane >> 2;
    const int tig  = lane & 3;
    const int wm   = warp >> 1;           // 0..3
    const int wn   = warp & 1;            // 0..1

    float C[2][8][4];
#pragma unroll
    for (int s = 0; s < 2; s++)
#pragma unroll
        for (int n = 0; n < 8; n++)
#pragma unroll
            for (int j = 0; j < 4; j++) C[s][n][j] = 0.f;

    for (int k0 = 0; k0 < K; k0 += 32) {
        // Stage A tile 128x32, split hi/lo
#pragma unroll
        for (int it = 0; it < 4; it++) {
            int idx = tid + it * 256;     // 0..1023
            int r   = idx >> 3;
            int c4  = (idx & 7) << 2;
            float4 v = *(const float4*)&X[(size_t)(bm + r) * K + k0 + c4];
            float4 h, l;
            h.x = tf32hi(v.x); l.x = v.x - h.x;
            h.y = tf32hi(v.y); l.y = v.y - h.y;
            h.z = tf32hi(v.z); l.z = v.z - h.z;
            h.w = tf32hi(v.w); l.w = v.w - h.w;
            *(float4*)&Ah[r * SA + c4] = h;
            *(float4*)&Al[r * SA + c4] = l;
        }
        // Stage B tile 32x128, split hi/lo
#pragma unroll
        for (int it = 0; it < 4; it++) {
            int idx = tid + it * 256;
            int r   = idx >> 5;
            int c4  = (idx & 31) << 2;
            float4 v = *(const float4*)&W[(size_t)(k0 + r) * N + bn + c4];
            float4 h, l;
            h.x = tf32hi(v.x); l.x = v.x - h.x;
            h.y = tf32hi(v.y); l.y = v.y - h.y;
            h.z = tf32hi(v.z); l.z = v.z - h.z;
            h.w = tf32hi(v.w); l.w = v.w - h.w;
            *(float4*)&Bh[r * SB + c4] = h;
            *(float4*)&Bl[r * SB + c4] = l;
        }
        __syncthreads();

#pragma unroll
        for (int kc = 0; kc < 4; kc++) {
            uint32_t ah[2][4], al[2][4];
#pragma unroll
            for (int s = 0; s < 2; s++) {
                int row = wm * 32 + s * 16 + g;
                int dc  = kc * 8 + tig;
                ah[s][0] = __float_as_uint(Ah[row * SA + dc]);
                ah[s][1] = __float_as_uint(Ah[(row + 8) * SA + dc]);
                ah[s][2] = __float_as_uint(Ah[row * SA + dc + 4]);
                ah[s][3] = __float_as_uint(Ah[(row + 8) * SA + dc + 4]);
                al[s][0] = __float_as_uint(Al[row * SA + dc]);
                al[s][1] = __float_as_uint(Al[(row + 8) * SA + dc]);
                al[s][2] = __float_as_uint(Al[row * SA + dc + 4]);
                al[s][3] = __float_as_uint(Al[(row + 8) * SA + dc + 4]);
            }
#pragma unroll
            for (int n = 0; n < 8; n++) {
                int col = wn * 64 + n * 8 + g;
                uint32_t bh[2], bl[2];
                bh[0] = __float_as_uint(Bh[(kc * 8 + tig) * SB + col]);
                bh[1] = __float_as_uint(Bh[(kc * 8 + tig + 4) * SB + col]);
                bl[0] = __float_as_uint(Bl[(kc * 8 + tig) * SB + col]);
                bl[1] = __float_as_uint(Bl[(kc * 8 + tig + 4) * SB + col]);
#pragma unroll
                for (int s = 0; s < 2; s++) {
                    mma8(C[s][n], ah[s], bh);
                    mma8(C[s][n], ah[s], bl);
                    mma8(C[s][n], al[s], bh);
                }
            }
        }
        __syncthreads();
    }

    // Epilogue
#pragma unroll
    for (int s = 0; s < 2; s++) {
#pragma unroll
        for (int n = 0; n < 8; n++) {
            int row = bm + wm * 32 + s * 16 + g;
            int col = bn + wn * 64 + n * 8 + 2 * tig;
            float b0 = bias[col], b1 = bias[col + 1];
            float2 o;
            o.x = (C[s][n][0] + b0) * scale;
            o.y = (C[s][n][1] + b1) * scale;
            *(float2*)&Y[(size_t)row * N + col] = o;
            o.x = (C[s][n][2] + b0) * scale;
            o.y = (C[s][n][3] + b1) * scale;
            *(float2*)&Y[(size_t)(row + 8) * N + col] = o;
        }
    }
}

// ---------------------------------------------------------------------------
// 3xTF32 flash attention. CTA = 128 q-rows, one (b,h). 8 warps, each warp
// owns 16 q-rows x all 64 keys of the tile. Online softmax in fragments.
// ---------------------------------------------------------------------------
#define SKV 68   // K/V smem row stride (floats)

__global__ __launch_bounds__(256, 1) void flash_tf32_kernel(
    const int* __restrict__ mask,
    const float* __restrict__ bias)
{
    extern __shared__ float sm[];
    float* Khi = sm;                  // [64][SKV]  (natural [key][d])
    float* Klo = sm + 64 * SKV;
    float* Vhi = sm + 2 * 64 * SKV;   // [64][SKV]  (natural [key][d])
    float* Vlo = sm + 3 * 64 * SKV;
    float* Qst = sm;                  // alias: [128][SKV] staging (= Khi+Klo)

    const int b    = blockIdx.x;
    const int q0   = blockIdx.y * 128;
    const int h    = blockIdx.z;
    const int tid  = threadIdx.x;
    const int warp = tid >> 5;
    const int lane = tid & 31;
    const int g    = lane >> 2;
    const int tig  = lane & 3;

    const float* Qg = g_Q + (size_t)b * SEQ * DMODEL + (size_t)h * HDIM;
    const float* Kg = g_K + (size_t)b * SEQ * DMODEL + (size_t)h * HDIM;
    const float* Vg = g_V + (size_t)b * SEQ * DMODEL + (size_t)h * HDIM;
    const float* biasH = bias + (size_t)h * SEQ * SEQ;

    // ---- Stage Q tile (raw fp32), then build resident Q fragments ----
#pragma unroll
    for (int it = 0; it < 8; it++) {
        int idx = tid + it * 256;          // 0..2047
        int r   = idx >> 4;
        int c4  = (idx & 15) << 2;
        *(float4*)&Qst[r * SKV + c4] =
            *(const float4*)&Qg[(size_t)(q0 + r) * DMODEL + c4];
    }
    __syncthreads();

    uint32_t qh[8][4], ql[8][4];
    const int r1 = warp * 16 + g;
    const int r2 = r1 + 8;
#pragma unroll
    for (int c = 0; c < 8; c++) {
        int dc = c * 8 + tig;
        float v0 = Qst[r1 * SKV + dc];
        float v1 = Qst[r2 * SKV + dc];
        float v2 = Qst[r1 * SKV + dc + 4];
        float v3 = Qst[r2 * SKV + dc + 4];
        float h0 = tf32hi(v0), h1 = tf32hi(v1), h2 = tf32hi(v2), h3 = tf32hi(v3);
        qh[c][0] = __float_as_uint(h0); ql[c][0] = __float_as_uint(v0 - h0);
        qh[c][1] = __float_as_uint(h1); ql[c][1] = __float_as_uint(v1 - h1);
        qh[c][2] = __float_as_uint(h2); ql[c][2] = __float_as_uint(v2 - h2);
        qh[c][3] = __float_as_uint(h3); ql[c][3] = __float_as_uint(v3 - h3);
    }
    __syncthreads();   // before K staging overwrites Qst

    float O[8][4];
#pragma unroll
    for (int n = 0; n < 8; n++)
#pragma unroll
        for (int j = 0; j < 4; j++) O[n][j] = 0.f;
    float m0 = -CUDART_INF_F, m1 = -CUDART_INF_F, l0 = 0.f, l1 = 0.f;

    const int row0 = q0 + warp * 16 + g;
    const int row1 = row0 + 8;

    for (int k0 = 0; k0 < SEQ; k0 += 64) {
        // ---- Stage K and V tiles, split hi/lo ----
#pragma unroll
        for (int it = 0; it < 4; it++) {
            int idx = tid + it * 256;       // 0..1023
            int r   = idx >> 4;             // key 0..63
            int c4  = (idx & 15) << 2;      // d
            float4 kv = *(const float4*)&Kg[(size_t)(k0 + r) * DMODEL + c4];
            float4 vv = *(const float4*)&Vg[(size_t)(k0 + r) * DMODEL + c4];
            float4 hh, ll;
            hh.x = tf32hi(kv.x); ll.x = kv.x - hh.x;
            hh.y = tf32hi(kv.y); ll.y = kv.y - hh.y;
            hh.z = tf32hi(kv.z); ll.z = kv.z - hh.z;
            hh.w = tf32hi(kv.w); ll.w = kv.w - hh.w;
            *(float4*)&Khi[r * SKV + c4] = hh;
            *(float4*)&Klo[r * SKV + c4] = ll;
            hh.x = tf32hi(vv.x); ll.x = vv.x - hh.x;
            hh.y = tf32hi(vv.y); ll.y = vv.y - hh.y;
            hh.z = tf32hi(vv.z); ll.z = vv.z - hh.z;
            hh.w = tf32hi(vv.w); ll.w = vv.w - hh.w;
            *(float4*)&Vhi[r * SKV + c4] = hh;
            *(float4*)&Vlo[r * SKV + c4] = ll;
        }
        __syncthreads();

        // ---- S = Q @ K^T (3xTF32) ----
        float S[8][4];
#pragma unroll
        for (int n = 0; n < 8; n++) {
            S[n][0] = S[n][1] = S[n][2] = S[n][3] = 0.f;
            int krow = n * 8 + g;
#pragma unroll
            for (int c = 0; c < 8; c++) {
                int dc = c * 8 + tig;
                uint32_t bh[2], bl[2];
                bh[0] = __float_as_uint(Khi[krow * SKV + dc]);
                bh[1] = __float_as_uint(Khi[krow * SKV + dc + 4]);
                bl[0] = __float_as_uint(Klo[krow * SKV + dc]);
                bl[1] = __float_as_uint(Klo[krow * SKV + dc + 4]);
                mma8(S[n], qh[c], bh);
                mma8(S[n], qh[c], bl);
                mma8(S[n], ql[c], bh);
            }
        }

        // ---- bias + mask ----
#pragma unroll
        for (int n = 0; n < 8; n++) {
            int col = k0 + n * 8 + 2 * tig;
            float2 bv0 = *(const float2*)&biasH[(size_t)row0 * SEQ + col];
            int2   mv0 = *(const int2*)  &mask [(size_t)row0 * SEQ + col];
            float2 bv1 = *(const float2*)&biasH[(size_t)row1 * SEQ + col];
            int2   mv1 = *(const int2*)  &mask [(size_t)row1 * SEQ + col];
            S[n][0] = mv0.x ? S[n][0] + bv0.x : -CUDART_INF_F;
            S[n][1] = mv0.y ? S[n][1] + bv0.y : -CUDART_INF_F;
            S[n][2] = mv1.x ? S[n][2] + bv1.x : -CUDART_INF_F;
            S[n][3] = mv1.y ? S[n][3] + bv1.y : -CUDART_INF_F;
        }

        // ---- online softmax (rows g / g+8, quad-wide reductions) ----
        float mx0 = -CUDART_INF_F, mx1 = -CUDART_INF_F;
#pragma unroll
        for (int n = 0; n < 8; n++) {
            mx0 = fmaxf(mx0, fmaxf(S[n][0], S[n][1]));
            mx1 = fmaxf(mx1, fmaxf(S[n][2], S[n][3]));
        }
        mx0 = fmaxf(mx0, __shfl_xor_sync(0xffffffffu, mx0, 1));
        mx0 = fmaxf(mx0, __shfl_xor_sync(0xffffffffu, mx0, 2));
        mx1 = fmaxf(mx1, __shfl_xor_sync(0xffffffffu, mx1, 1));
        mx1 = fmaxf(mx1, __shfl_xor_sync(0xffffffffu, mx1, 2));

        float mn0 = fmaxf(m0, mx0), mn1 = fmaxf(m1, mx1);
        float ref0 = (mn0 == -CUDART_INF_F) ? 0.f : mn0;
        float ref1 = (mn1 == -CUDART_INF_F) ? 0.f : mn1;
        float alpha0 = __expf(m0 - ref0);
        float alpha1 = __expf(m1 - ref1);
        m0 = mn0; m1 = mn1;

        float rs0 = 0.f, rs1 = 0.f;
#pragma unroll
        for (int n = 0; n < 8; n++) {
            S[n][0] = __expf(S[n][0] - ref0);
            S[n][1] = __expf(S[n][1] - ref0);
            S[n][2] = __expf(S[n][2] - ref1);
            S[n][3] = __expf(S[n][3] - ref1);
            rs0 += S[n][0] + S[n][1];
            rs1 += S[n][2] + S[n][3];
        }
        rs0 += __shfl_xor_sync(0xffffffffu, rs0, 1);
        rs0 += __shfl_xor_sync(0xffffffffu, rs0, 2);
        rs1 += __shfl_xor_sync(0xffffffffu, rs1, 1);
        rs1 += __shfl_xor_sync(0xffffffffu, rs1, 2);
        l0 = l0 * alpha0 + rs0;
        l1 = l1 * alpha1 + rs1;

#pragma unroll
        for (int n = 0; n < 8; n++) {
            O[n][0] *= alpha0; O[n][1] *= alpha0;
            O[n][2] *= alpha1; O[n][3] *= alpha1;
        }

        // ---- O += P @ V (3xTF32). P A-frags assembled via quad shuffles ----
        const int srcA = (g << 2) | (tig >> 1);
        const int srcB = srcA + 2;
        const bool sel = tig & 1;
#pragma unroll
        for (int c = 0; c < 8; c++) {
            float vA0 = __shfl_sync(0xffffffffu, S[c][0], srcA);
            float vA1 = __shfl_sync(0xffffffffu, S[c][1], srcA);
            float vA2 = __shfl_sync(0xffffffffu, S[c][2], srcA);
            float vA3 = __shfl_sync(0xffffffffu, S[c][3], srcA);
            float vB0 = __shfl_sync(0xffffffffu, S[c][0], srcB);
            float vB1 = __shfl_sync(0xffffffffu, S[c][1], srcB);
            float vB2 = __shfl_sync(0xffffffffu, S[c][2], srcB);
            float vB3 = __shfl_sync(0xffffffffu, S[c][3], srcB);
            float pa0 = sel ? vA1 : vA0;   // (row g,   key c*8+tig)
            float pa1 = sel ? vA3 : vA2;   // (row g+8, key c*8+tig)
            float pa2 = sel ? vB1 : vB0;   // (row g,   key c*8+tig+4)
            float pa3 = sel ? vB3 : vB2;   // (row g+8, key c*8+tig+4)
            uint32_t pah[4], pal[4];
            float h0 = tf32hi(pa0), h1 = tf32hi(pa1), h2 = tf32hi(pa2), h3 = tf32hi(pa3);
            pah[0] = __float_as_uint(h0); pal[0] = __float_as_uint(pa0 - h0);
            pah[1] = __float_as_uint(h1); pal[1] = __float_as_uint(pa1 - h1);
            pah[2] = __float_as_uint(h2); pal[2] = __float_as_uint(pa2 - h2);
            pah[3] = __float_as_uint(h3); pal[3] = __float_as_uint(pa3 - h3);

            int vrow = c * 8 + tig;   // key
#pragma unroll
            for (int n = 0; n < 8; n++) {
                int vcol = n * 8 + g; // d
                uint32_t bh[2], bl[2];
                bh[0] = __float_as_uint(Vhi[vrow * SKV + vcol]);
                bh[1] = __float_as_uint(Vhi[(vrow + 4) * SKV + vcol]);
                bl[0] = __float_as_uint(Vlo[vrow * SKV + vcol]);
                bl[1] = __float_as_uint(Vlo[(vrow + 4) * SKV + vcol]);
                mma8(O[n], pah, bh);
                mma8(O[n], pah, bl);
                mma8(O[n], pal, bh);
            }
        }
        __syncthreads();   // before next tile's staging
    }

    // ---- epilogue: normalize, write ctx [b, s, h*64+d] ----
    float inv0 = (l0 > 0.f) ? (1.f / l0) : 0.f;
    float inv1 = (l1 > 0.f) ? (1.f / l1) : 0.f;
#pragma unroll
    for (int n = 0; n < 8; n++) {
        int col = h * HDIM + n * 8 + 2 * tig;
        float2 o;
        o.x = O[n][0] * inv0; o.y = O[n][1] * inv0;
        *(float2*)&g_CTX[(size_t)(b * SEQ + row0) * DMODEL + col] = o;
        o.x = O[n][2] * inv1; o.y = O[n][3] * inv1;
        *(float2*)&g_CTX[(size_t)(b * SEQ + row1) * DMODEL + col] = o;
    }
}

// ---------------------------------------------------------------------------
// Launch
// ---------------------------------------------------------------------------
extern "C" void kernel_launch(void* const* d_in, const int* in_sizes, int n_in,
                              void* d_out, int out_size)
{
    const float* k    = (const float*)d_in[0];
    const float* v    = (const float*)d_in[1];
    const float* q    = (const float*)d_in[2];
    const int*   mask = (const int*)d_in[3];
    const float* bias = (const float*)d_in[4];
    const float* Wq   = (const float*)d_in[5];
    const float* bq   = (const float*)d_in[6];
    const float* Wk   = (const float*)d_in[7];
    const float* bk   = (const float*)d_in[8];
    const float* Wv   = (const float*)d_in[9];
    const float* bv   = (const float*)d_in[10];
    const float* Wo   = (const float*)d_in[11];
    const float* bo   = (const float*)d_in[12];
    float* out = (float*)d_out;

    float *pQ, *pK, *pV, *pC;
    cudaGetSymbolAddress((void**)&pQ, g_Q);
    cudaGetSymbolAddress((void**)&pK, g_K);
    cudaGetSymbolAddress((void**)&pV, g_V);
    cudaGetSymbolAddress((void**)&pC, g_CTX);

    const int gemm_smem = (2 * 128 * SA + 2 * 32 * SB) * 4;   // 71680 B
    const int attn_smem = 4 * 64 * SKV * 4;                    // 69632 B
    cudaFuncSetAttribute(gemm_tf32_kernel,
                         cudaFuncAttributeMaxDynamicSharedMemorySize, gemm_smem);
    cudaFuncSetAttribute(flash_tf32_kernel,
                         cudaFuncAttributeMaxDynamicSharedMemorySize, attn_smem);

    const int M = BATCH * SEQ;                 // 4096
    dim3 gemm_grid(DMODEL / 128, M / 128);     // (4, 32)
    const float qscale = 0.125f;               // 1/sqrt(64)

    gemm_tf32_kernel<<<gemm_grid, 256, gemm_smem>>>(q, Wq, bq, pQ, M, DMODEL, DMODEL, qscale);
    gemm_tf32_kernel<<<gemm_grid, 256, gemm_smem>>>(k, Wk, bk, pK, M, DMODEL, DMODEL, 1.0f);
    gemm_tf32_kernel<<<gemm_grid, 256, gemm_smem>>>(v, Wv, bv, pV, M, DMODEL, DMODEL, 1.0f);

    dim3 attn_grid(BATCH, SEQ / 128, NHEADS);  // batch fastest -> bias L2 reuse
    flash_tf32_kernel<<<attn_grid, 256, attn_smem>>>(mask, bias);

    gemm_tf32_kernel<<<gemm_grid, 256, gemm_smem>>>(pC, Wo, bo, out, M, DMODEL, DMODEL, 1.0f);
}

// round 9
// speedup vs baseline: 2.0340x; 1.1801x over previous
#include <cuda_runtime.h>
#include <math_constants.h>
#include <cstdint>

#define SEQ    2048
#define BATCH  2
#define NHEADS 8
#define DMODEL 512
#define HDIM   64

// Scratch (allocation-free): 4 x 8MB
__device__ float g_Q[BATCH * SEQ * DMODEL];
__device__ float g_K[BATCH * SEQ * DMODEL];
__device__ float g_V[BATCH * SEQ * DMODEL];
__device__ float g_CTX[BATCH * SEQ * DMODEL];

// ---------------------------------------------------------------------------
// tf32 helpers
// ---------------------------------------------------------------------------
__device__ __forceinline__ float tf32hi(float x) {
    uint32_t u;
    asm("cvt.rna.tf32.f32 %0, %1;" : "=r"(u) : "f"(x));
    return __uint_as_float(u);
}
__device__ __forceinline__ uint32_t tf32u(float x) {
    uint32_t u;
    asm("cvt.rna.tf32.f32 %0, %1;" : "=r"(u) : "f"(x));
    return u;
}

// D += A * B  (m16n8k8, row.col, tf32 in / f32 accum)
__device__ __forceinline__ void mma8(float* c, const uint32_t* a, const uint32_t* b) {
    asm volatile(
        "mma.sync.aligned.m16n8k8.row.col.f32.tf32.tf32.f32 "
        "{%0,%1,%2,%3}, {%4,%5,%6,%7}, {%8,%9}, {%0,%1,%2,%3};"
        : "+f"(c[0]), "+f"(c[1]), "+f"(c[2]), "+f"(c[3])
        : "r"(a[0]), "r"(a[1]), "r"(a[2]), "r"(a[3]), "r"(b[0]), "r"(b[1]));
}

// ---------------------------------------------------------------------------
// 3xTF32 GEMM: Y[M,N] = (X[M,K] @ W[K,N] + bias[N]) * scale
// 128x128 tile, BK=32, 256 threads = 8 warps (4m x 2n), warp tile 32x64.
// ---------------------------------------------------------------------------
#define SA 36    // A smem row stride (floats)
#define SB 136   // B smem row stride (floats)

__global__ __launch_bounds__(256) void gemm_tf32_kernel(
    const float* __restrict__ X, const float* __restrict__ W,
    const float* __restrict__ bias, float* __restrict__ Y,
    int M, int N, int K, float scale)
{
    extern __shared__ float sm[];
    float* Ah = sm;                       // [128][SA]
    float* Al = sm + 128 * SA;
    float* Bh = sm + 2 * 128 * SA;        // [32][SB]
    float* Bl = sm + 2 * 128 * SA + 32 * SB;

    const int bm   = blockIdx.y * 128;
    const int bn   = blockIdx.x * 128;
    const int tid  = threadIdx.x;
    const int warp = tid >> 5;
    const int lane = tid & 31;
    const int g    = lane >> 2;
    const int tig  = lane & 3;
    const int wm   = warp >> 1;           // 0..3
    const int wn   = warp & 1;            // 0..1

    float C[2][8][4];
#pragma unroll
    for (int s = 0; s < 2; s++)
#pragma unroll
        for (int n = 0; n < 8; n++)
#pragma unroll
            for (int j = 0; j < 4; j++) C[s][n][j] = 0.f;

    for (int k0 = 0; k0 < K; k0 += 32) {
        // Stage A tile 128x32, split hi/lo
#pragma unroll
        for (int it = 0; it < 4; it++) {
            int idx = tid + it * 256;     // 0..1023
            int r   = idx >> 3;
            int c4  = (idx & 7) << 2;
            float4 v = *(const float4*)&X[(size_t)(bm + r) * K + k0 + c4];
            float4 h, l;
            h.x = tf32hi(v.x); l.x = v.x - h.x;
            h.y = tf32hi(v.y); l.y = v.y - h.y;
            h.z = tf32hi(v.z); l.z = v.z - h.z;
            h.w = tf32hi(v.w); l.w = v.w - h.w;
            *(float4*)&Ah[r * SA + c4] = h;
            *(float4*)&Al[r * SA + c4] = l;
        }
        // Stage B tile 32x128, split hi/lo
#pragma unroll
        for (int it = 0; it < 4; it++) {
            int idx = tid + it * 256;
            int r   = idx >> 5;
            int c4  = (idx & 31) << 2;
            float4 v = *(const float4*)&W[(size_t)(k0 + r) * N + bn + c4];
            float4 h, l;
            h.x = tf32hi(v.x); l.x = v.x - h.x;
            h.y = tf32hi(v.y); l.y = v.y - h.y;
            h.z = tf32hi(v.z); l.z = v.z - h.z;
            h.w = tf32hi(v.w); l.w = v.w - h.w;
            *(float4*)&Bh[r * SB + c4] = h;
            *(float4*)&Bl[r * SB + c4] = l;
        }
        __syncthreads();

#pragma unroll
        for (int kc = 0; kc < 4; kc++) {
            uint32_t ah[2][4], al[2][4];
#pragma unroll
            for (int s = 0; s < 2; s++) {
                int row = wm * 32 + s * 16 + g;
                int dc  = kc * 8 + tig;
                ah[s][0] = __float_as_uint(Ah[row * SA + dc]);
                ah[s][1] = __float_as_uint(Ah[(row + 8) * SA + dc]);
                ah[s][2] = __float_as_uint(Ah[row * SA + dc + 4]);
                ah[s][3] = __float_as_uint(Ah[(row + 8) * SA + dc + 4]);
                al[s][0] = __float_as_uint(Al[row * SA + dc]);
                al[s][1] = __float_as_uint(Al[(row + 8) * SA + dc]);
                al[s][2] = __float_as_uint(Al[row * SA + dc + 4]);
                al[s][3] = __float_as_uint(Al[(row + 8) * SA + dc + 4]);
            }
#pragma unroll
            for (int n = 0; n < 8; n++) {
                int col = wn * 64 + n * 8 + g;
                uint32_t bh[2], bl[2];
                bh[0] = __float_as_uint(Bh[(kc * 8 + tig) * SB + col]);
                bh[1] = __float_as_uint(Bh[(kc * 8 + tig + 4) * SB + col]);
                bl[0] = __float_as_uint(Bl[(kc * 8 + tig) * SB + col]);
                bl[1] = __float_as_uint(Bl[(kc * 8 + tig + 4) * SB + col]);
#pragma unroll
                for (int s = 0; s < 2; s++) {
                    mma8(C[s][n], ah[s], bh);
                    mma8(C[s][n], ah[s], bl);
                    mma8(C[s][n], al[s], bh);
                }
            }
        }
        __syncthreads();
    }

    // Epilogue
#pragma unroll
    for (int s = 0; s < 2; s++) {
#pragma unroll
        for (int n = 0; n < 8; n++) {
            int row = bm + wm * 32 + s * 16 + g;
            int col = bn + wn * 64 + n * 8 + 2 * tig;
            float b0 = bias[col], b1 = bias[col + 1];
            float2 o;
            o.x = (C[s][n][0] + b0) * scale;
            o.y = (C[s][n][1] + b1) * scale;
            *(float2*)&Y[(size_t)row * N + col] = o;
            o.x = (C[s][n][2] + b0) * scale;
            o.y = (C[s][n][3] + b1) * scale;
            *(float2*)&Y[(size_t)(row + 8) * N + col] = o;
        }
    }
}

// ---------------------------------------------------------------------------
// Flash attention, tensor-core. CTA = 128 q-rows, one (b,h). 8 warps x 16 rows.
// QK: Q rounded-to-tf32 (1 frag) x K split hi/lo = 2 mmas  (err ~1.5e-4 abs)
// PV: P split hi/lo x V rounded-to-tf32        = 2 mmas  (err ~1.4e-4 rel)
// Q fragments kept in SMEM (raw fp32, cvt at frag load) to cut registers.
// __launch_bounds__(256,2): 2 CTAs/SM, grid 256 = one resident wave.
// ---------------------------------------------------------------------------
#define SKV 68   // smem row stride (floats)

__global__ __launch_bounds__(256, 2) void flash_tf32_kernel(
    const int* __restrict__ mask,
    const float* __restrict__ bias)
{
    extern __shared__ float sm[];
    float* Qraw = sm;                    // [128][SKV] raw fp32
    float* Khi  = sm + 128 * SKV;        // [64][SKV]
    float* Klo  = Khi + 64 * SKV;
    float* Vhi  = Klo + 64 * SKV;        // [64][SKV] rounded V

    const int b    = blockIdx.x;
    const int q0   = blockIdx.y * 128;
    const int h    = blockIdx.z;
    const int tid  = threadIdx.x;
    const int warp = tid >> 5;
    const int lane = tid & 31;
    const int g    = lane >> 2;
    const int tig  = lane & 3;

    const float* Qg = g_Q + (size_t)b * SEQ * DMODEL + (size_t)h * HDIM;
    const float* Kg = g_K + (size_t)b * SEQ * DMODEL + (size_t)h * HDIM;
    const float* Vg = g_V + (size_t)b * SEQ * DMODEL + (size_t)h * HDIM;
    const float* biasH = bias + (size_t)h * SEQ * SEQ;

    // ---- Stage Q tile once (raw fp32) ----
#pragma unroll
    for (int it = 0; it < 8; it++) {
        int idx = tid + it * 256;          // 0..2047
        int r   = idx >> 4;
        int c4  = (idx & 15) << 2;
        *(float4*)&Qraw[r * SKV + c4] =
            *(const float4*)&Qg[(size_t)(q0 + r) * DMODEL + c4];
    }
    // (sync provided by the one inside the k-loop before first compute)

    float O[8][4];
#pragma unroll
    for (int n = 0; n < 8; n++)
#pragma unroll
        for (int j = 0; j < 4; j++) O[n][j] = 0.f;
    float m0 = -CUDART_INF_F, m1 = -CUDART_INF_F, l0 = 0.f, l1 = 0.f;

    const int r1   = warp * 16 + g;        // CTA-local q-row (frag rows)
    const int r2   = r1 + 8;
    const int row0 = q0 + r1;              // global q-rows (bias/mask)
    const int row1 = row0 + 8;

    for (int k0 = 0; k0 < SEQ; k0 += 64) {
        // ---- Stage K (split hi/lo) and V (rounded) ----
#pragma unroll
        for (int it = 0; it < 4; it++) {
            int idx = tid + it * 256;       // 0..1023
            int r   = idx >> 4;             // key 0..63
            int c4  = (idx & 15) << 2;      // d
            float4 kv = *(const float4*)&Kg[(size_t)(k0 + r) * DMODEL + c4];
            float4 vv = *(const float4*)&Vg[(size_t)(k0 + r) * DMODEL + c4];
            float4 hh, ll;
            hh.x = tf32hi(kv.x); ll.x = kv.x - hh.x;
            hh.y = tf32hi(kv.y); ll.y = kv.y - hh.y;
            hh.z = tf32hi(kv.z); ll.z = kv.z - hh.z;
            hh.w = tf32hi(kv.w); ll.w = kv.w - hh.w;
            *(float4*)&Khi[r * SKV + c4] = hh;
            *(float4*)&Klo[r * SKV + c4] = ll;
            hh.x = tf32hi(vv.x); hh.y = tf32hi(vv.y);
            hh.z = tf32hi(vv.z); hh.w = tf32hi(vv.w);
            *(float4*)&Vhi[r * SKV + c4] = hh;
        }
        __syncthreads();

        // ---- S = Q @ K^T (Q rounded x K hi/lo) ----
        float S[8][4];
#pragma unroll
        for (int n = 0; n < 8; n++)
            S[n][0] = S[n][1] = S[n][2] = S[n][3] = 0.f;

#pragma unroll
        for (int c = 0; c < 8; c++) {
            int dc = c * 8 + tig;
            uint32_t a[4];
            a[0] = tf32u(Qraw[r1 * SKV + dc]);
            a[1] = tf32u(Qraw[r2 * SKV + dc]);
            a[2] = tf32u(Qraw[r1 * SKV + dc + 4]);
            a[3] = tf32u(Qraw[r2 * SKV + dc + 4]);
#pragma unroll
            for (int n = 0; n < 8; n++) {
                int krow = n * 8 + g;
                uint32_t bh[2], bl[2];
                bh[0] = __float_as_uint(Khi[krow * SKV + dc]);
                bh[1] = __float_as_uint(Khi[krow * SKV + dc + 4]);
                bl[0] = __float_as_uint(Klo[krow * SKV + dc]);
                bl[1] = __float_as_uint(Klo[krow * SKV + dc + 4]);
                mma8(S[n], a, bh);
                mma8(S[n], a, bl);
            }
        }

        // ---- bias + mask ----
#pragma unroll
        for (int n = 0; n < 8; n++) {
            int col = k0 + n * 8 + 2 * tig;
            float2 bv0 = *(const float2*)&biasH[(size_t)row0 * SEQ + col];
            int2   mv0 = *(const int2*)  &mask [(size_t)row0 * SEQ + col];
            float2 bv1 = *(const float2*)&biasH[(size_t)row1 * SEQ + col];
            int2   mv1 = *(const int2*)  &mask [(size_t)row1 * SEQ + col];
            S[n][0] = mv0.x ? S[n][0] + bv0.x : -CUDART_INF_F;
            S[n][1] = mv0.y ? S[n][1] + bv0.y : -CUDART_INF_F;
            S[n][2] = mv1.x ? S[n][2] + bv1.x : -CUDART_INF_F;
            S[n][3] = mv1.y ? S[n][3] + bv1.y : -CUDART_INF_F;
        }

        // ---- online softmax (rows g / g+8, quad-wide reductions) ----
        float mx0 = -CUDART_INF_F, mx1 = -CUDART_INF_F;
#pragma unroll
        for (int n = 0; n < 8; n++) {
            mx0 = fmaxf(mx0, fmaxf(S[n][0], S[n][1]));
            mx1 = fmaxf(mx1, fmaxf(S[n][2], S[n][3]));
        }
        mx0 = fmaxf(mx0, __shfl_xor_sync(0xffffffffu, mx0, 1));
        mx0 = fmaxf(mx0, __shfl_xor_sync(0xffffffffu, mx0, 2));
        mx1 = fmaxf(mx1, __shfl_xor_sync(0xffffffffu, mx1, 1));
        mx1 = fmaxf(mx1, __shfl_xor_sync(0xffffffffu, mx1, 2));

        float mn0 = fmaxf(m0, mx0), mn1 = fmaxf(m1, mx1);
        float ref0 = (mn0 == -CUDART_INF_F) ? 0.f : mn0;
        float ref1 = (mn1 == -CUDART_INF_F) ? 0.f : mn1;
        float alpha0 = __expf(m0 - ref0);
        float alpha1 = __expf(m1 - ref1);
        m0 = mn0; m1 = mn1;

        float rs0 = 0.f, rs1 = 0.f;
#pragma unroll
        for (int n = 0; n < 8; n++) {
            S[n][0] = __expf(S[n][0] - ref0);
            S[n][1] = __expf(S[n][1] - ref0);
            S[n][2] = __expf(S[n][2] - ref1);
            S[n][3] = __expf(S[n][3] - ref1);
            rs0 += S[n][0] + S[n][1];
            rs1 += S[n][2] + S[n][3];
        }
        rs0 += __shfl_xor_sync(0xffffffffu, rs0, 1);
        rs0 += __shfl_xor_sync(0xffffffffu, rs0, 2);
        rs1 += __shfl_xor_sync(0xffffffffu, rs1, 1);
        rs1 += __shfl_xor_sync(0xffffffffu, rs1, 2);
        l0 = l0 * alpha0 + rs0;
        l1 = l1 * alpha1 + rs1;

#pragma unroll
        for (int n = 0; n < 8; n++) {
            O[n][0] *= alpha0; O[n][1] *= alpha0;
            O[n][2] *= alpha1; O[n][3] *= alpha1;
        }

        // ---- O += P @ V (P hi/lo x V rounded). A-frags via quad shuffles ----
        const int srcA = (g << 2) | (tig >> 1);
        const int srcB = srcA + 2;
        const bool sel = tig & 1;
#pragma unroll
        for (int c = 0; c < 8; c++) {
            float vA0 = __shfl_sync(0xffffffffu, S[c][0], srcA);
            float vA1 = __shfl_sync(0xffffffffu, S[c][1], srcA);
            float vA2 = __shfl_sync(0xffffffffu, S[c][2], srcA);
            float vA3 = __shfl_sync(0xffffffffu, S[c][3], srcA);
            float vB0 = __shfl_sync(0xffffffffu, S[c][0], srcB);
            float vB1 = __shfl_sync(0xffffffffu, S[c][1], srcB);
            float vB2 = __shfl_sync(0xffffffffu, S[c][2], srcB);
            float vB3 = __shfl_sync(0xffffffffu, S[c][3], srcB);
            float pa0 = sel ? vA1 : vA0;   // (row g,   key c*8+tig)
            float pa1 = sel ? vA3 : vA2;   // (row g+8, key c*8+tig)
            float pa2 = sel ? vB1 : vB0;   // (row g,   key c*8+tig+4)
            float pa3 = sel ? vB3 : vB2;   // (row g+8, key c*8+tig+4)
            uint32_t pah[4], pal[4];
            float h0 = tf32hi(pa0), h1 = tf32hi(pa1), h2 = tf32hi(pa2), h3 = tf32hi(pa3);
            pah[0] = __float_as_uint(h0); pal[0] = __float_as_uint(pa0 - h0);
            pah[1] = __float_as_uint(h1); pal[1] = __float_as_uint(pa1 - h1);
            pah[2] = __float_as_uint(h2); pal[2] = __float_as_uint(pa2 - h2);
            pah[3] = __float_as_uint(h3); pal[3] = __float_as_uint(pa3 - h3);

            int vrow = c * 8 + tig;   // key
#pragma unroll
            for (int n = 0; n < 8; n++) {
                int vcol = n * 8 + g; // d
                uint32_t bh[2];
                bh[0] = __float_as_uint(Vhi[vrow * SKV + vcol]);
                bh[1] = __float_as_uint(Vhi[(vrow + 4) * SKV + vcol]);
                mma8(O[n], pah, bh);
                mma8(O[n], pal, bh);
            }
        }
        __syncthreads();   // before next tile's staging
    }

    // ---- epilogue: normalize, write ctx [b, s, h*64+d] ----
    float inv0 = (l0 > 0.f) ? (1.f / l0) : 0.f;
    float inv1 = (l1 > 0.f) ? (1.f / l1) : 0.f;
#pragma unroll
    for (int n = 0; n < 8; n++) {
        int col = h * HDIM + n * 8 + 2 * tig;
        float2 o;
        o.x = O[n][0] * inv0; o.y = O[n][1] * inv0;
        *(float2*)&g_CTX[(size_t)(b * SEQ + row0) * DMODEL + col] = o;
        o.x = O[n][2] * inv1; o.y = O[n][3] * inv1;
        *(float2*)&g_CTX[(size_t)(b * SEQ + row1) * DMODEL + col] = o;
    }
}

// ---------------------------------------------------------------------------
// Launch
// ---------------------------------------------------------------------------
extern "C" void kernel_launch(void* const* d_in, const int* in_sizes, int n_in,
                              void* d_out, int out_size)
{
    const float* k    = (const float*)d_in[0];
    const float* v    = (const float*)d_in[1];
    const float* q    = (const float*)d_in[2];
    const int*   mask = (const int*)d_in[3];
    const float* bias = (const float*)d_in[4];
    const float* Wq   = (const float*)d_in[5];
    const float* bq   = (const float*)d_in[6];
    const float* Wk   = (const float*)d_in[7];
    const float* bk   = (const float*)d_in[8];
    const float* Wv   = (const float*)d_in[9];
    const float* bv   = (const float*)d_in[10];
    const float* Wo   = (const float*)d_in[11];
    const float* bo   = (const float*)d_in[12];
    float* out = (float*)d_out;

    float *pQ, *pK, *pV, *pC;
    cudaGetSymbolAddress((void**)&pQ, g_Q);
    cudaGetSymbolAddress((void**)&pK, g_K);
    cudaGetSymbolAddress((void**)&pV, g_V);
    cudaGetSymbolAddress((void**)&pC, g_CTX);

    const int gemm_smem = (2 * 128 * SA + 2 * 32 * SB) * 4;   // 71680 B
    const int attn_smem = (128 + 3 * 64) * SKV * 4;            // 87040 B
    cudaFuncSetAttribute(gemm_tf32_kernel,
                         cudaFuncAttributeMaxDynamicSharedMemorySize, gemm_smem);
    cudaFuncSetAttribute(flash_tf32_kernel,
                         cudaFuncAttributeMaxDynamicSharedMemorySize, attn_smem);

    const int M = BATCH * SEQ;                 // 4096
    dim3 gemm_grid(DMODEL / 128, M / 128);     // (4, 32)
    const float qscale = 0.125f;               // 1/sqrt(64)

    gemm_tf32_kernel<<<gemm_grid, 256, gemm_smem>>>(q, Wq, bq, pQ, M, DMODEL, DMODEL, qscale);
    gemm_tf32_kernel<<<gemm_grid, 256, gemm_smem>>>(k, Wk, bk, pK, M, DMODEL, DMODEL, 1.0f);
    gemm_tf32_kernel<<<gemm_grid, 256, gemm_smem>>>(v, Wv, bv, pV, M, DMODEL, DMODEL, 1.0f);

    dim3 attn_grid(BATCH, SEQ / 128, NHEADS);  // batch fastest -> bias L2 reuse
    flash_tf32_kernel<<<attn_grid, 256, attn_smem>>>(mask, bias);

    gemm_tf32_kernel<<<gemm_grid, 256, gemm_smem>>>(pC, Wo, bo, out, M, DMODEL, DMODEL, 1.0f);
}